// round 2
// baseline (speedup 1.0000x reference)
#include <cuda_runtime.h>
#include <cstdint>

#define U_N 100000
#define I_N 50000
#define HD  128
#define E_N 600000
#define EL_N 200000

// ---------------- scratch (device globals: allocation-free) ----------------
__device__ float g_agg_u[(size_t)U_N * HD];   // 51.2 MB
__device__ float g_agg_i[(size_t)I_N * HD];   // 25.6 MB
__device__ float g_u1[(size_t)U_N * HD];
__device__ float g_i1[(size_t)I_N * HD];
__device__ float g_u2[(size_t)U_N * HD];
__device__ float g_i2[(size_t)I_N * HD];
__device__ float g_deg_u[U_N];
__device__ float g_deg_i[I_N];

// Vector reduction to global (sm_90+): 4x fewer L2 atomic ops than scalar atomicAdd.
__device__ __forceinline__ void red_add_v4(float* addr, float4 v) {
    asm volatile("red.global.add.v4.f32 [%0], {%1, %2, %3, %4};"
                 :: "l"(addr), "f"(v.x), "f"(v.y), "f"(v.z), "f"(v.w)
                 : "memory");
}

// ---------------- zero ----------------
__global__ void zero_f4(float4* __restrict__ p, int n4) {
    int i = blockIdx.x * blockDim.x + threadIdx.x;
    int stride = gridDim.x * blockDim.x;
    float4 z = make_float4(0.f, 0.f, 0.f, 0.f);
    for (; i < n4; i += stride) p[i] = z;
}

// ---------------- edge scatter (both directions fused; 1 warp / edge) ------
__global__ void scatter_kernel(float* __restrict__ agg_u, float* __restrict__ agg_i,
                               float* __restrict__ deg_u, float* __restrict__ deg_i,
                               const float* __restrict__ xu, const float* __restrict__ xi,
                               const int* __restrict__ ei, int do_deg) {
    int e = blockIdx.x * (blockDim.x >> 5) + (threadIdx.x >> 5);
    if (e >= E_N) return;
    int lane = threadIdx.x & 31;
    int u  = ei[e];          // broadcast load
    int it = ei[E_N + e];

    float4 vi = ((const float4*)(xi + (size_t)it * HD))[lane];
    red_add_v4(agg_u + (size_t)u * HD + lane * 4, vi);

    float4 vu = ((const float4*)(xu + (size_t)u * HD))[lane];
    red_add_v4(agg_i + (size_t)it * HD + lane * 4, vu);

    if (do_deg && lane == 0) {
        atomicAdd(deg_u + u, 1.0f);
        atomicAdd(deg_i + it, 1.0f);
    }
}

// ---------------- fused SAGE transform -------------------------------------
// out[M x 128] = opt_relu( (agg/max(deg,1)) @ Wl + b + x @ Wr )
// Treated as [M x 256] @ [256 x 128]; BK=32 tiles land entirely in agg-half
// (kt<4, scaled) or x-half (kt>=4).
template <bool RELU>
__global__ __launch_bounds__(256)
void sage_gemm(const float* __restrict__ agg, const float* __restrict__ deg,
               const float* __restrict__ x,
               const float* __restrict__ Wl, const float* __restrict__ Wr,
               const float* __restrict__ bias, float* __restrict__ out, int M) {
    __shared__ float As[64][36];    // [row][k], padded for .128 alignment
    __shared__ float Bs[32][128];   // [k][col]

    const int tid = threadIdx.x;
    const int tx = tid & 31;        // col group: cols tx*4 .. tx*4+3
    const int ty = tid >> 5;        // row group: rows ty*8 .. ty*8+7
    const int row0 = blockIdx.x * 64;

    float acc[8][4];
#pragma unroll
    for (int i = 0; i < 8; i++)
#pragma unroll
        for (int j = 0; j < 4; j++) acc[i][j] = 0.f;

#pragma unroll 1
    for (int kt = 0; kt < 8; kt++) {
        const bool isAgg = kt < 4;
        const int kbase = (kt & 3) * 32;
        const float* __restrict__ A = isAgg ? agg : x;
        const float* __restrict__ W = isAgg ? Wl : Wr;

        // load A tile: 64 rows x 32 k  (512 float4, 2 per thread)
#pragma unroll
        for (int rep = 0; rep < 2; rep++) {
            int fid = tid + rep * 256;      // 0..511
            int r   = fid >> 3;             // 0..63
            int c4  = fid & 7;              // float4 idx within 32 k
            int grow = row0 + r;
            float4 v = make_float4(0.f, 0.f, 0.f, 0.f);
            if (grow < M) {
                v = ((const float4*)(A + (size_t)grow * HD + kbase))[c4];
                if (isAgg) {
                    float invd = 1.0f / fmaxf(deg[grow], 1.0f);
                    v.x *= invd; v.y *= invd; v.z *= invd; v.w *= invd;
                }
            }
            *(float4*)&As[r][c4 * 4] = v;
        }
        // load B tile: 32 k x 128 cols (1024 float4, 4 per thread)
#pragma unroll
        for (int rep = 0; rep < 4; rep++) {
            int fid = tid + rep * 256;      // 0..1023
            int kk  = fid >> 5;             // 0..31
            int c4  = fid & 31;             // 0..31
            *(float4*)&Bs[kk][c4 * 4] =
                ((const float4*)(W + (size_t)(kbase + kk) * HD))[c4];
        }
        __syncthreads();

#pragma unroll
        for (int kk = 0; kk < 32; kk++) {
            float a[8];
#pragma unroll
            for (int i = 0; i < 8; i++) a[i] = As[ty * 8 + i][kk];  // broadcast
            float4 b4 = *(const float4*)&Bs[kk][tx * 4];
            float b[4] = {b4.x, b4.y, b4.z, b4.w};
#pragma unroll
            for (int i = 0; i < 8; i++)
#pragma unroll
                for (int j = 0; j < 4; j++) acc[i][j] += a[i] * b[j];
        }
        __syncthreads();
    }

    float4 bb = ((const float4*)bias)[tx];
#pragma unroll
    for (int i = 0; i < 8; i++) {
        int grow = row0 + ty * 8 + i;
        if (grow < M) {
            float4 o;
            o.x = acc[i][0] + bb.x;
            o.y = acc[i][1] + bb.y;
            o.z = acc[i][2] + bb.z;
            o.w = acc[i][3] + bb.w;
            if (RELU) {
                o.x = fmaxf(o.x, 0.f); o.y = fmaxf(o.y, 0.f);
                o.z = fmaxf(o.z, 0.f); o.w = fmaxf(o.w, 0.f);
            }
            *(float4*)(out + (size_t)grow * HD + tx * 4) = o;
        }
    }
}

// ---------------- edge dot-product classifier ------------------------------
__global__ void classify_kernel(const float* __restrict__ u2, const float* __restrict__ i2,
                                const int* __restrict__ lbl, float* __restrict__ out) {
    int e = blockIdx.x * (blockDim.x >> 5) + (threadIdx.x >> 5);
    if (e >= EL_N) return;
    int lane = threadIdx.x & 31;
    int u  = lbl[e];
    int it = lbl[EL_N + e];
    float4 a = ((const float4*)(u2 + (size_t)u * HD))[lane];
    float4 b = ((const float4*)(i2 + (size_t)it * HD))[lane];
    float s = a.x * b.x + a.y * b.y + a.z * b.z + a.w * b.w;
#pragma unroll
    for (int o = 16; o > 0; o >>= 1) s += __shfl_xor_sync(0xFFFFFFFFu, s, o);
    if (lane == 0) out[e] = s;
}

// ---------------- launch ----------------------------------------------------
extern "C" void kernel_launch(void* const* d_in, const int* in_sizes, int n_in,
                              void* d_out, int out_size) {
    const float* user_emb = (const float*)d_in[0];
    const float* item_emb = (const float*)d_in[1];
    const float* w1_ui_l = (const float*)d_in[2];
    const float* w1_ui_r = (const float*)d_in[3];
    const float* w1_iu_l = (const float*)d_in[4];
    const float* w1_iu_r = (const float*)d_in[5];
    const float* w2_ui_l = (const float*)d_in[6];
    const float* w2_ui_r = (const float*)d_in[7];
    const float* w2_iu_l = (const float*)d_in[8];
    const float* w2_iu_r = (const float*)d_in[9];
    const float* b1_ui = (const float*)d_in[10];
    const float* b1_iu = (const float*)d_in[11];
    const float* b2_ui = (const float*)d_in[12];
    const float* b2_iu = (const float*)d_in[13];
    // d_in[14]=user_node_id (arange), d_in[15]=item_node_id (arange) -- identity
    const int* ei_ui = (const int*)d_in[16];   // [src_u ; dst_i], also serves iu direction
    const int* lbl   = (const int*)d_in[18];
    float* out = (float*)d_out;

    float *agg_u, *agg_i, *u1, *i1, *u2, *i2, *deg_u, *deg_i;
    cudaGetSymbolAddress((void**)&agg_u, g_agg_u);
    cudaGetSymbolAddress((void**)&agg_i, g_agg_i);
    cudaGetSymbolAddress((void**)&u1, g_u1);
    cudaGetSymbolAddress((void**)&i1, g_i1);
    cudaGetSymbolAddress((void**)&u2, g_u2);
    cudaGetSymbolAddress((void**)&i2, g_i2);
    cudaGetSymbolAddress((void**)&deg_u, g_deg_u);
    cudaGetSymbolAddress((void**)&deg_i, g_deg_i);

    const int ZB = 256;
    // ---- layer 1 ----
    zero_f4<<<4096, ZB>>>((float4*)agg_u, U_N * HD / 4);
    zero_f4<<<2048, ZB>>>((float4*)agg_i, I_N * HD / 4);
    zero_f4<<<128, ZB>>>((float4*)deg_u, U_N / 4);
    zero_f4<<<64, ZB>>>((float4*)deg_i, I_N / 4);

    scatter_kernel<<<(E_N + 7) / 8, 256>>>(agg_u, agg_i, deg_u, deg_i,
                                           user_emb, item_emb, ei_ui, 1);

    // u1 = relu(mean(items->u) @ w1_iu_l + b1_iu + xu @ w1_iu_r)
    sage_gemm<true><<<(U_N + 63) / 64, 256>>>(agg_u, deg_u, user_emb,
                                              w1_iu_l, w1_iu_r, b1_iu, u1, U_N);
    // i1 = relu(mean(users->i) @ w1_ui_l + b1_ui + xi @ w1_ui_r)
    sage_gemm<true><<<(I_N + 63) / 64, 256>>>(agg_i, deg_i, item_emb,
                                              w1_ui_l, w1_ui_r, b1_ui, i1, I_N);

    // ---- layer 2 ----
    zero_f4<<<4096, ZB>>>((float4*)agg_u, U_N * HD / 4);
    zero_f4<<<2048, ZB>>>((float4*)agg_i, I_N * HD / 4);

    scatter_kernel<<<(E_N + 7) / 8, 256>>>(agg_u, agg_i, deg_u, deg_i,
                                           u1, i1, ei_ui, 0);

    sage_gemm<false><<<(U_N + 63) / 64, 256>>>(agg_u, deg_u, u1,
                                               w2_iu_l, w2_iu_r, b2_iu, u2, U_N);
    sage_gemm<false><<<(I_N + 63) / 64, 256>>>(agg_i, deg_i, i1,
                                               w2_ui_l, w2_ui_r, b2_ui, i2, I_N);

    // ---- classifier ----
    classify_kernel<<<(EL_N + 7) / 8, 256>>>(u2, i2, lbl, out);
}